// round 10
// baseline (speedup 1.0000x reference)
#include <cuda_runtime.h>
#include <cuda_fp16.h>
#include <math.h>
#include <stdint.h>

#define B 16
#define CIN 512
#define COUT 512
#define HH 64
#define WW 64
#define SS 512
#define SCALE2 (1.0f / 4608.0f)

// ---------------- scratch (__device__ globals) ----------------
__device__ float g_s[B * CIN];
__device__ float g_demod[B * COUT];
__device__ float g_wsq[COUT * CIN];
// Winograd-transformed input, fp16 half2(ci even, ci odd), B-fragment order:
// word addr = ((t*32 + chunk)*16384 + n)*8 + p ; n = b*1024 + ty*32 + tx
__device__ __align__(16) uint32_t g_Dt[(size_t)16 * 32 * 16384 * 8];
// Winograd weights, fp16 A-fragment order, 64-co slabs:
// word addr = ((mt8*16 + t)*32 + chunk)*512 + wq*256 + im*128 + lane*4 + j
__device__ __align__(16) uint32_t g_wtA[8 * 16 * 32 * 512];

// ---------------- PTX helpers ----------------
__device__ __forceinline__ uint32_t smem_u32(const void* p) {
    uint32_t a;
    asm("{ .reg .u64 t; cvta.to.shared.u64 t, %1; cvt.u32.u64 %0, t; }" : "=r"(a) : "l"(p));
    return a;
}
#define MBAR_INIT(a, n) asm volatile("mbarrier.init.shared.b64 [%0], %1;" :: "r"(a), "r"(n) : "memory")
#define MBAR_EXPECT(a, tx) asm volatile("mbarrier.arrive.expect_tx.shared.b64 _, [%0], %1;" :: "r"(a), "r"(tx) : "memory")
#define MBAR_WAIT(a, ph) do {                                                             \
    uint32_t _m = (a), _p = (ph);                                                         \
    asm volatile("{ .reg .pred P; WL%=:\n\t"                                              \
        "mbarrier.try_wait.parity.acquire.cta.shared::cta.b64 P, [%0], %1, 0x989680;\n\t" \
        "@P bra.uni WD%=;\n\t bra.uni WL%=;\n\t WD%=: }" :: "r"(_m), "r"(_p) : "memory"); \
} while (0)
#define FENCE_ASYNC() asm volatile("fence.proxy.async.shared::cta;" ::: "memory")
#define BULK_CP(dst, src, sz, mb)                                                              \
    asm volatile("cp.async.bulk.shared::cta.global.mbarrier::complete_tx::bytes [%0], [%1], %2, [%3];" \
        :: "r"(dst), "l"(src), "r"(sz), "r"(mb) : "memory")
#define MMA_F16(d, a, b0v, b1v)                                                            \
    asm volatile(                                                                          \
        "mma.sync.aligned.m16n8k16.row.col.f32.f16.f16.f32 "                               \
        "{%0,%1,%2,%3}, {%4,%5,%6,%7}, {%8,%9}, {%0,%1,%2,%3};"                            \
        : "+f"(d[0]), "+f"(d[1]), "+f"(d[2]), "+f"(d[3])                                   \
        : "r"(a.x), "r"(a.y), "r"(a.z), "r"(a.w), "r"(b0v), "r"(b1v))

// ---------------- prep kernels (proven) ----------------
__global__ void k_style(const float* __restrict__ style, const float* __restrict__ mod_w,
                        const float* __restrict__ mod_b) {
    __shared__ float ss[SS];
    const int b = blockIdx.x, lane = threadIdx.x & 31, warp = threadIdx.x >> 5;
    const int ci = blockIdx.y * 8 + warp;
    for (int i = threadIdx.x; i < SS; i += 256) ss[i] = style[b * SS + i];
    __syncthreads();
    const float* wr = mod_w + (size_t)ci * SS;
    float p = 0.f;
    #pragma unroll 4
    for (int j = lane; j < SS; j += 32) p = fmaf(wr[j], ss[j], p);
    #pragma unroll
    for (int o = 16; o > 0; o >>= 1) p += __shfl_xor_sync(0xffffffffu, p, o);
    if (lane == 0) g_s[b * CIN + ci] = p + mod_b[ci];
}

__global__ void k_wsq(const float* __restrict__ weight) {
    int idx = blockIdx.x * blockDim.x + threadIdx.x;
    if (idx >= COUT * CIN) return;
    const float* w = weight + (size_t)idx * 9;
    float s = 0.f;
    #pragma unroll
    for (int k = 0; k < 9; k++) s = fmaf(w[k], w[k], s);
    g_wsq[idx] = s;
}

__global__ void k_demod() {
    int wid = (blockIdx.x * blockDim.x + threadIdx.x) >> 5;
    int lane = threadIdx.x & 31;
    int b = wid >> 9, co = wid & 511;
    const float* wsq = g_wsq + (size_t)co * CIN;
    const float* sr = g_s + (size_t)b * CIN;
    float p = 0.f;
    #pragma unroll 4
    for (int j = lane; j < CIN; j += 32) { float sv = sr[j]; p = fmaf(wsq[j], sv * sv, p); }
    #pragma unroll
    for (int o = 16; o > 0; o >>= 1) p += __shfl_xor_sync(0xffffffffu, p, o);
    if (lane == 0) g_demod[b * COUT + co] = rsqrtf(SCALE2 * p + 1e-8f);
}

// ---------------- Winograd weight transform -> 64-co A-frag slabs ----------
__global__ void k_winW(const float* __restrict__ weight) {
    int idx = blockIdx.x * 256 + threadIdx.x;     // 512 co * 256 pairs
    int co = idx >> 8, p = idx & 255;
    float Wt[2][4][4];
    #pragma unroll
    for (int h = 0; h < 2; h++) {
        int ci = 2 * p + h;
        const float* w = weight + ((size_t)co * CIN + ci) * 9;
        float tg[4][3];
        #pragma unroll
        for (int c = 0; c < 3; c++) {
            float w0 = w[c], w1 = w[3 + c], w2 = w[6 + c];
            tg[0][c] = w0;
            tg[1][c] = 0.5f * (w0 + w1 + w2);
            tg[2][c] = 0.5f * (w0 - w1 + w2);
            tg[3][c] = w2;
        }
        #pragma unroll
        for (int r = 0; r < 4; r++) {
            Wt[h][r][0] = tg[r][0];
            Wt[h][r][1] = 0.5f * (tg[r][0] + tg[r][1] + tg[r][2]);
            Wt[h][r][2] = 0.5f * (tg[r][0] - tg[r][1] + tg[r][2]);
            Wt[h][r][3] = tg[r][2];
        }
    }
    int chunk = p >> 3, pp = p & 7, tt = pp & 3, kh = pp >> 2;
    int mt8 = co >> 6, co_l = co & 63;
    int g = co_l & 7, mh = (co_l >> 3) & 1, im = (co_l >> 4) & 1, wq = (co_l >> 5) & 1;
    int lane = g * 4 + tt, j = mh | (kh << 1);
    #pragma unroll
    for (int t = 0; t < 16; t++) {
        __half2 h = __floats2half2_rn(Wt[0][t >> 2][t & 3], Wt[1][t >> 2][t & 3]);
        g_wtA[(size_t)((mt8 * 16 + t) * 32 + chunk) * 512 + wq * 256 + im * 128 + lane * 4 + j]
            = *(uint32_t*)&h;
    }
}

// ---------------- Winograd input transform (proven) ----------------
__global__ void k_winD(const float* __restrict__ input) {
    __shared__ float sm[4 * 66 * 16];
    const int ty = blockIdx.x;            // 0..31
    const int chunk = blockIdx.y;         // 0..31
    const int b = blockIdx.z;             // 0..15
    const int tid = threadIdx.x;

    if (tid < 128) {
        int r = (tid >> 4) & 3, ci = tid & 15, c = (tid < 64) ? 0 : 65;
        sm[(r * 66 + c) * 16 + ci] = 0.f;
    }
    const float* in_b = input + ((size_t)b * CIN + chunk * 16) * 4096;
    const float* sv = g_s + b * CIN + chunk * 16;
    for (int i = tid; i < 4096; i += 256) {
        int x = i & 63, r = (i >> 6) & 3, ci = i >> 8;
        int gy = 2 * ty - 1 + r;
        float v = 0.f;
        if (gy >= 0 && gy < HH) v = in_b[(size_t)ci * 4096 + gy * 64 + x] * __ldg(sv + ci);
        sm[(r * 66 + x + 1) * 16 + ci] = v;
    }
    __syncthreads();

    const int tx = tid >> 3, p = tid & 7;
    float2 d[4][4];
    #pragma unroll
    for (int r = 0; r < 4; r++)
        #pragma unroll
        for (int c = 0; c < 4; c++)
            d[r][c] = *(const float2*)&sm[(r * 66 + 2 * tx + c) * 16 + 2 * p];

    float2 tmp[4][4];
    #pragma unroll
    for (int c = 0; c < 4; c++) {
        tmp[0][c] = make_float2(d[0][c].x - d[2][c].x, d[0][c].y - d[2][c].y);
        tmp[1][c] = make_float2(d[1][c].x + d[2][c].x, d[1][c].y + d[2][c].y);
        tmp[2][c] = make_float2(d[2][c].x - d[1][c].x, d[2][c].y - d[1][c].y);
        tmp[3][c] = make_float2(d[1][c].x - d[3][c].x, d[1][c].y - d[3][c].y);
    }
    const int n = b * 1024 + ty * 32 + tx;
    #pragma unroll
    for (int r = 0; r < 4; r++) {
        float2 D[4];
        D[0] = make_float2(tmp[r][0].x - tmp[r][2].x, tmp[r][0].y - tmp[r][2].y);
        D[1] = make_float2(tmp[r][1].x + tmp[r][2].x, tmp[r][1].y + tmp[r][2].y);
        D[2] = make_float2(tmp[r][2].x - tmp[r][1].x, tmp[r][2].y - tmp[r][1].y);
        D[3] = make_float2(tmp[r][1].x - tmp[r][3].x, tmp[r][1].y - tmp[r][3].y);
        #pragma unroll
        for (int c = 0; c < 4; c++) {
            int t = r * 4 + c;
            __half2 h = __floats2half2_rn(D[c].x, D[c].y);
            g_Dt[(((size_t)(t * 32 + chunk)) * 16384 + n) * 8 + p] = *(uint32_t*)&h;
        }
    }
}

// ---------------- fused Winograd GEMM + inverse transform ----------------
// CTA: 64 co (mt8) x 128 n (nb). 8 warps: wq = wid>>2 (32co), wn = wid&3 (32n).
// 16 taps x 16 (2-kstep) stages = 256 stages; 8-deep bulk ring; fold per tap
// into 128-float register OUT; epilogue writes 2x2 tiles directly.
#define WOFF 128
#define WSTG 12288                        // A 4KB + B 8KB
#define WRING 8
#define WSMEM (WOFF + WRING * WSTG)       // 98432

__global__ void __launch_bounds__(256, 1)
k_wfused(float* __restrict__ out) {
    extern __shared__ char smem[];
    const uint32_t sb = smem_u32(smem);
    const int tid = threadIdx.x, lane = tid & 31, wid = tid >> 5;
    const int wq = wid >> 2, wn = wid & 3;
    const int g = lane >> 2, tt = lane & 3;
    const int mt8 = blockIdx.x;    // 0..7
    const int nb = blockIdx.y;     // 0..127
    const int b = nb >> 3;
    const int ty = (nb & 7) * 4 + wn;

    if (tid < WRING) MBAR_INIT(sb + 16 + tid * 8, 1);
    __syncthreads();

    const uint32_t* gA = g_wtA + (size_t)(mt8 * 16) * 32 * 512;
    const uint32_t* gB = g_Dt + (size_t)nb * 128 * 8;

    #define WISSUE(st) do {                                                               \
        int _sl = (st) & 7; uint32_t _mb = sb + 16 + _sl * 8;                             \
        int _t = (st) >> 4, _kk = (st) & 15;                                              \
        MBAR_EXPECT(_mb, 12288);                                                          \
        BULK_CP(sb + WOFF + _sl * WSTG,                                                   \
                (const void*)(gA + (size_t)(_t * 32 + 2 * _kk) * 512), 4096, _mb);        \
        BULK_CP(sb + WOFF + _sl * WSTG + 4096,                                            \
                (const void*)(gB + (size_t)(_t * 32 + 2 * _kk) * 16384 * 8), 4096, _mb);  \
        BULK_CP(sb + WOFF + _sl * WSTG + 8192,                                            \
                (const void*)(gB + (size_t)(_t * 32 + 2 * _kk + 1) * 16384 * 8), 4096, _mb); \
    } while (0)

    if (tid == 0) {
        FENCE_ASYNC();
        #pragma unroll
        for (int s = 0; s < WRING; s++) WISSUE(s);
    }

    float OUT[128];
    #pragma unroll
    for (int i = 0; i < 128; i++) OUT[i] = 0.f;
    float acc[2][4][4];
    #pragma unroll
    for (int im = 0; im < 2; im++)
        #pragma unroll
        for (int nf = 0; nf < 4; nf++)
            #pragma unroll
            for (int c = 0; c < 4; c++) acc[im][nf][c] = 0.f;

    const float AT0[4] = {1.f, 1.f, 1.f, 0.f};
    const float AT1[4] = {0.f, 1.f, -1.f, -1.f};

    #pragma unroll
    for (int t = 0; t < 16; t++) {
        #pragma unroll 2
        for (int kk = 0; kk < 16; kk++) {
            const int st = t * 16 + kk;
            MBAR_WAIT(sb + 16 + (st & 7) * 8, (st >> 3) & 1);
            const uint32_t* sA = (const uint32_t*)(smem + WOFF + (st & 7) * WSTG);
            #pragma unroll
            for (int ks = 0; ks < 2; ks++) {
                const uint32_t* ap = sA + ks * 512 + wq * 256 + lane * 4;
                uint4 A0 = *(const uint4*)(ap);
                uint4 A1 = *(const uint4*)(ap + 128);
                const uint32_t* bp = sA + 1024 + ks * 1024 + (wn * 32 + g) * 8 + tt;
                #pragma unroll
                for (int nf = 0; nf < 4; nf++) {
                    uint32_t b0 = bp[nf * 64];
                    uint32_t b1 = bp[nf * 64 + 4];
                    MMA_F16(acc[0][nf], A0, b0, b1);
                    MMA_F16(acc[1][nf], A1, b0, b1);
                }
            }
            __syncthreads();
            if (tid == 0 && st + WRING < 256) WISSUE(st + WRING);
        }
        // fold tap t into OUT (compile-time coefficients; zeros elided)
        const int u = t >> 2, v = t & 3;
        const float c0 = AT0[u] * AT0[v], c1 = AT0[u] * AT1[v];
        const float c2 = AT1[u] * AT0[v], c3 = AT1[u] * AT1[v];
        #pragma unroll
        for (int im = 0; im < 2; im++)
            #pragma unroll
            for (int nf = 0; nf < 4; nf++)
                #pragma unroll
                for (int cc = 0; cc < 4; cc++) {
                    const float a = acc[im][nf][cc];
                    const int e4 = ((im * 4 + nf) * 4 + cc) * 4;
                    if (c0 != 0.f) OUT[e4 + 0] += c0 * a;
                    if (c1 != 0.f) OUT[e4 + 1] += c1 * a;
                    if (c2 != 0.f) OUT[e4 + 2] += c2 * a;
                    if (c3 != 0.f) OUT[e4 + 3] += c3 * a;
                    acc[im][nf][cc] = 0.f;
                }
    }
    #undef WISSUE

    // ---- epilogue: scale * demod, direct 2x2-tile float4 stores ----
    const float scale = rsqrtf(4608.0f);
    #pragma unroll
    for (int im = 0; im < 2; im++)
        #pragma unroll
        for (int h = 0; h < 2; h++) {
            const int co = mt8 * 64 + wq * 32 + im * 16 + g + h * 8;
            const float f = scale * __ldg(&g_demod[b * COUT + co]);
            #pragma unroll
            for (int nf = 0; nf < 4; nf++) {
                const int e0 = ((im * 4 + nf) * 4 + h * 2) * 4;     // e=0 cell
                const int e1 = e0 + 4;                               // e=1 cell
                #pragma unroll
                for (int i = 0; i < 2; i++) {
                    const int row = 2 * ty + i;
                    float4 vv;
                    vv.x = OUT[e0 + i * 2 + 0] * f;
                    vv.y = OUT[e0 + i * 2 + 1] * f;
                    vv.z = OUT[e1 + i * 2 + 0] * f;
                    vv.w = OUT[e1 + i * 2 + 1] * f;
                    *(float4*)(out + (((size_t)(b * COUT + co)) * 64 + row) * 64
                               + nf * 16 + tt * 4) = vv;
                }
            }
        }
}

// ---------------------------------------------------------------------------
extern "C" void kernel_launch(void* const* d_in, const int* in_sizes, int n_in,
                              void* d_out, int out_size) {
    const float* input  = (const float*)d_in[0];
    const float* style  = (const float*)d_in[1];
    const float* weight = (const float*)d_in[2];
    const float* mod_w  = (const float*)d_in[3];
    const float* mod_b  = (const float*)d_in[4];
    float* out = (float*)d_out;

    static int smem_set = 0;
    if (!smem_set) {
        cudaFuncSetAttribute(k_wfused, cudaFuncAttributeMaxDynamicSharedMemorySize, WSMEM);
        smem_set = 1;
    }

    k_style<<<dim3(16, 64), 256>>>(style, mod_w, mod_b);
    k_wsq<<<(COUT * CIN + 255) / 256, 256>>>(weight);
    k_winW<<<512, 256>>>(weight);
    k_demod<<<1024, 256>>>();
    k_winD<<<dim3(32, 32, 16), 256>>>(input);
    k_wfused<<<dim3(8, 128), 256, WSMEM>>>(out);
}

// round 11
// speedup vs baseline: 1.7358x; 1.7358x over previous
#include <cuda_runtime.h>
#include <cuda_fp16.h>
#include <math.h>
#include <stdint.h>

#define B 16
#define CIN 512
#define COUT 512
#define HH 64
#define WW 64
#define SS 512
#define SCALE2 (1.0f / 4608.0f)

// ---------------- scratch (__device__ globals) ----------------
__device__ float g_s[B * CIN];
__device__ float g_demod[B * COUT];
__device__ float g_wsq[COUT * CIN];
// modulated fp16 input, chunk-major, padded halo, 12-word pixel rows:
// [b][chunk(32)][yp(66)][xh(66)][word(12)]; word j<8 = ciPair j, j>=8 pad
__device__ __align__(16) uint32_t g_inh[(size_t)B * 32 * 66 * 792];
// fp16 weights in per-thread A-fragment order:
// [mt(4)][chunk(32)][tap(9)][wm(2)][mtile(4)][lane(32)][j(4)] uint32 (half2 ci pair)
__device__ __align__(16) uint32_t g_wfA[4 * 32 * 9 * 2 * 4 * 128];

// ---------------- PTX helpers ----------------
__device__ __forceinline__ uint32_t smem_u32(const void* p) {
    uint32_t a;
    asm("{ .reg .u64 t; cvta.to.shared.u64 t, %1; cvt.u32.u64 %0, t; }" : "=r"(a) : "l"(p));
    return a;
}
#define MBAR_INIT(a, n) asm volatile("mbarrier.init.shared.b64 [%0], %1;" :: "r"(a), "r"(n) : "memory")
#define MBAR_EXPECT(a, tx) asm volatile("mbarrier.arrive.expect_tx.shared.b64 _, [%0], %1;" :: "r"(a), "r"(tx) : "memory")
#define MBAR_WAIT(a, ph) do {                                                             \
    uint32_t _m = (a), _p = (ph);                                                         \
    asm volatile("{ .reg .pred P; WL%=:\n\t"                                              \
        "mbarrier.try_wait.parity.acquire.cta.shared::cta.b64 P, [%0], %1, 0x989680;\n\t" \
        "@P bra.uni WD%=;\n\t bra.uni WL%=;\n\t WD%=: }" :: "r"(_m), "r"(_p) : "memory"); \
} while (0)
#define FENCE_ASYNC() asm volatile("fence.proxy.async.shared::cta;" ::: "memory")
#define BULK_CP(dst, src, sz, mb)                                                              \
    asm volatile("cp.async.bulk.shared::cta.global.mbarrier::complete_tx::bytes [%0], [%1], %2, [%3];" \
        :: "r"(dst), "l"(src), "r"(sz), "r"(mb) : "memory")
#define MMA_F16(d, a, b0v, b1v)                                                            \
    asm volatile(                                                                          \
        "mma.sync.aligned.m16n8k16.row.col.f32.f16.f16.f32 "                               \
        "{%0,%1,%2,%3}, {%4,%5,%6,%7}, {%8,%9}, {%0,%1,%2,%3};"                            \
        : "+f"(d[0]), "+f"(d[1]), "+f"(d[2]), "+f"(d[3])                                   \
        : "r"(a.x), "r"(a.y), "r"(a.z), "r"(a.w), "r"(b0v), "r"(b1v))

// ---------------- prep kernels ----------------
__global__ void k_style(const float* __restrict__ style, const float* __restrict__ mod_w,
                        const float* __restrict__ mod_b) {
    __shared__ float ss[SS];
    const int b = blockIdx.x, lane = threadIdx.x & 31, warp = threadIdx.x >> 5;
    const int ci = blockIdx.y * 8 + warp;
    for (int i = threadIdx.x; i < SS; i += 256) ss[i] = style[b * SS + i];
    __syncthreads();
    const float* wr = mod_w + (size_t)ci * SS;
    float p = 0.f;
    #pragma unroll 4
    for (int j = lane; j < SS; j += 32) p = fmaf(wr[j], ss[j], p);
    #pragma unroll
    for (int o = 16; o > 0; o >>= 1) p += __shfl_xor_sync(0xffffffffu, p, o);
    if (lane == 0) g_s[b * CIN + ci] = p + mod_b[ci];
}

__global__ void k_wsq(const float* __restrict__ weight) {
    int idx = blockIdx.x * blockDim.x + threadIdx.x;
    if (idx >= COUT * CIN) return;
    const float* w = weight + (size_t)idx * 9;
    float s = 0.f;
    #pragma unroll
    for (int k = 0; k < 9; k++) s = fmaf(w[k], w[k], s);
    g_wsq[idx] = s;
}

__global__ void k_demod() {
    int wid = (blockIdx.x * blockDim.x + threadIdx.x) >> 5;
    int lane = threadIdx.x & 31;
    int b = wid >> 9, co = wid & 511;
    const float* wsq = g_wsq + (size_t)co * CIN;
    const float* sr = g_s + (size_t)b * CIN;
    float p = 0.f;
    #pragma unroll 4
    for (int j = lane; j < CIN; j += 32) { float sv = sr[j]; p = fmaf(wsq[j], sv * sv, p); }
    #pragma unroll
    for (int o = 16; o > 0; o >>= 1) p += __shfl_xor_sync(0xffffffffu, p, o);
    if (lane == 0) g_demod[b * COUT + co] = rsqrtf(SCALE2 * p + 1e-8f);
}

// modulated input -> fp16 chunk-major padded layout, 12-word pixel rows
__global__ void k_inh(const float* __restrict__ input) {
    __shared__ float sm[16][64];
    const int yp = blockIdx.x;      // 0..65 (rows 0 and 65 are zero borders)
    const int chunk = blockIdx.y;   // 0..31
    const int b = blockIdx.z;       // 0..15
    uint32_t* dst = g_inh + (((size_t)(b * 32 + chunk) * 66 + yp) * 792);
    if (yp == 0 || yp == 65) {
        for (int i = threadIdx.x; i < 792; i += 256) dst[i] = 0;
        return;
    }
    const int y = yp - 1;
    const float* sbv = g_s + b * CIN + chunk * 16;
    const float* src = input + ((size_t)b * CIN + chunk * 16) * 4096 + y * 64;
    for (int i = threadIdx.x; i < 1024; i += 256) {
        int ci = i >> 6, x = i & 63;
        sm[ci][x] = src[(size_t)ci * 4096 + x] * __ldg(sbv + ci);
    }
    __syncthreads();
    for (int i = threadIdx.x; i < 792; i += 256) {
        int xh = i / 12, j = i % 12;
        uint32_t w = 0;
        if (j < 8 && xh >= 1 && xh <= 64) {
            __half2 h = __floats2half2_rn(sm[2 * j][xh - 1], sm[2 * j + 1][xh - 1]);
            w = *(uint32_t*)&h;
        }
        dst[i] = w;
    }
}

// weights -> fp16 A-fragment-major slabs (proven layout)
__global__ void k_wfA(const float* __restrict__ weight) {
    int idx = blockIdx.x * blockDim.x + threadIdx.x;
    if (idx >= 4 * 32 * 9 * 1024) return;
    int j     = idx & 3;
    int lane  = (idx >> 2) & 31;
    int mtile = (idx >> 7) & 3;
    int wm    = (idx >> 9) & 1;
    int t     = (idx >> 10) % 9;
    int rest  = (idx >> 10) / 9;
    int chunk = rest & 31, mt = rest >> 5;
    int g = lane >> 2, tt = lane & 3;
    int co = mt * 128 + wm * 64 + mtile * 16 + g + (j & 1) * 8;
    int ci = chunk * 16 + 2 * tt + (j >> 1) * 8;
    const float* wp = weight + ((size_t)co * CIN + ci) * 9 + t;
    __half2 h = __floats2half2_rn(wp[0], wp[9]);   // (ci, ci+1) at tap t
    g_wfA[idx] = *(uint32_t*)&h;
}

// ---------------- main conv: fp16 mma.sync implicit GEMM, all-bulk staging --
// CTA: 128 co (mt) x 128 px (2 rows x 64 cols), 256 threads, 8 warps 2m x 4n.
// B smem rows are 12 words -> bank index (12g + tt) mod 32 hits all 32 banks.
#define NCHUNK 32
#define A_SLAB 36864               // 9*2*4*128*4 bytes
#define B_SLAB 12672               // 4 rows * 66 px * 12 words * 4B
#define OFF_A 64
#define OFF_B (OFF_A + 2 * A_SLAB)          // 73792
#define SMEM_TOTAL (OFF_B + 2 * B_SLAB)     // 99136

__global__ void __launch_bounds__(256, 2)
k_conv(float* __restrict__ out) {
    extern __shared__ char smem[];
    const uint32_t sb = smem_u32(smem);
    const int tid = threadIdx.x, lane = tid & 31, wid = tid >> 5;
    const int wm = wid >> 2, wn = wid & 3;
    const int yl = wn >> 1, xw = (wn & 1) * 32;
    const int g = lane >> 2, tt = lane & 3;

    const int mt = blockIdx.x;
    const int y0 = blockIdx.y * 2;
    const int b  = blockIdx.z;

    if (tid == 0) { MBAR_INIT(sb + 0, 1); MBAR_INIT(sb + 8, 1); }
    __syncthreads();

    const uint32_t* gA = g_wfA + (size_t)mt * 32 * 9216;
    const uint32_t* gB = g_inh + (size_t)b * 32 * 66 * 792;

    if (tid == 0) {
        FENCE_ASYNC();
        #pragma unroll
        for (int k = 0; k < 2; k++) {
            uint32_t mb = sb + k * 8;
            MBAR_EXPECT(mb, A_SLAB + B_SLAB);
            BULK_CP(sb + OFF_A + k * A_SLAB, (const void*)(gA + (size_t)k * 9216), A_SLAB, mb);
            BULK_CP(sb + OFF_B + k * B_SLAB, (const void*)(gB + ((size_t)k * 66 + y0) * 792), B_SLAB, mb);
        }
    }

    float acc[4][4][4];
    #pragma unroll
    for (int m = 0; m < 4; m++)
        #pragma unroll
        for (int n = 0; n < 4; n++)
            #pragma unroll
            for (int c = 0; c < 4; c++) acc[m][n][c] = 0.f;

    for (int c = 0; c < NCHUNK; c++) {
        MBAR_WAIT(sb + (c & 1) * 8, (c >> 1) & 1);
        const uint32_t* sA = (const uint32_t*)(smem + OFF_A + (c & 1) * A_SLAB);
        const uint32_t* sB = (const uint32_t*)(smem + OFF_B + (c & 1) * B_SLAB);

        #pragma unroll
        for (int tap = 0; tap < 9; tap++) {
            const int dy = tap / 3, dx = tap % 3;
            const int r = yl + dy;
            const uint32_t* ap = sA + (tap * 2 + wm) * 512 + lane * 4;
            uint4 A0 = *(const uint4*)(ap);
            uint4 A1 = *(const uint4*)(ap + 128);
            uint4 A2 = *(const uint4*)(ap + 256);
            uint4 A3 = *(const uint4*)(ap + 384);
            const uint32_t* bp = sB + (size_t)(r * 66 + xw + dx + g) * 12 + tt;
            #pragma unroll
            for (int nf = 0; nf < 4; nf++) {
                uint32_t b0 = bp[nf * 96];
                uint32_t b1 = bp[nf * 96 + 4];
                MMA_F16(acc[0][nf], A0, b0, b1);
                MMA_F16(acc[1][nf], A1, b0, b1);
                MMA_F16(acc[2][nf], A2, b0, b1);
                MMA_F16(acc[3][nf], A3, b0, b1);
            }
        }
        __syncthreads();
        if (tid == 0 && c + 2 < NCHUNK) {
            const int k = c + 2;
            uint32_t mb = sb + (k & 1) * 8;
            MBAR_EXPECT(mb, A_SLAB + B_SLAB);
            BULK_CP(sb + OFF_A + (k & 1) * A_SLAB, (const void*)(gA + (size_t)k * 9216), A_SLAB, mb);
            BULK_CP(sb + OFF_B + (k & 1) * B_SLAB, (const void*)(gB + ((size_t)k * 66 + y0) * 792), B_SLAB, mb);
        }
    }

    // ---- epilogue: scale * demod, float2 stores ----
    const float scale = rsqrtf(4608.0f);
    const int y = y0 + yl;
    #pragma unroll
    for (int im = 0; im < 4; im++) {
        const int coA = mt * 128 + wm * 64 + im * 16 + g;
        const float fA = g_demod[b * COUT + coA] * scale;
        const float fB = g_demod[b * COUT + coA + 8] * scale;
        const size_t base = ((((size_t)b * COUT + coA) << 6) + y) << 6;
        #pragma unroll
        for (int nf = 0; nf < 4; nf++) {
            const int x = xw + nf * 8 + 2 * tt;
            float2 lo = make_float2(acc[im][nf][0] * fA, acc[im][nf][1] * fA);
            float2 hi = make_float2(acc[im][nf][2] * fB, acc[im][nf][3] * fB);
            *(float2*)(out + base + x) = lo;
            *(float2*)(out + base + ((size_t)8 << 12) + x) = hi;   // co+8 plane
        }
    }
}

// ---------------------------------------------------------------------------
extern "C" void kernel_launch(void* const* d_in, const int* in_sizes, int n_in,
                              void* d_out, int out_size) {
    const float* input  = (const float*)d_in[0];
    const float* style  = (const float*)d_in[1];
    const float* weight = (const float*)d_in[2];
    const float* mod_w  = (const float*)d_in[3];
    const float* mod_b  = (const float*)d_in[4];
    float* out = (float*)d_out;

    static int smem_set = 0;
    if (!smem_set) {
        cudaFuncSetAttribute(k_conv, cudaFuncAttributeMaxDynamicSharedMemorySize, SMEM_TOTAL);
        smem_set = 1;
    }

    k_style<<<dim3(16, 64), 256>>>(style, mod_w, mod_b);
    k_wsq<<<(COUT * CIN + 255) / 256, 256>>>(weight);
    k_wfA<<<(4 * 32 * 9 * 1024 + 255) / 256, 256>>>(weight);
    k_demod<<<1024, 256>>>();
    k_inh<<<dim3(66, 32, 16), 256>>>(input);
    k_conv<<<dim3(4, 32, 16), 256, SMEM_TOTAL>>>(out);
}